// round 6
// baseline (speedup 1.0000x reference)
#include <cuda_runtime.h>
#include <cuda_bf16.h>

// Problem constants
constexpr int B  = 32;
constexpr int T  = 4096;
constexpr int D  = 1024;
constexpr int H  = 8;
constexpr int HD = 128;
constexpr int P  = 1024;

// GEMM tiling for the energy kernel
constexpr int KC  = 32;   // K chunk per stage
constexpr int KST = 40;   // padded smem row stride (bf16 elems) -> conflict-free frag LDS

// Device scratch (allocation-free rule: __device__ globals)
__device__ float g_q[B * P];            // relu(dec @ phi_w^T + phi_b)
__device__ float g_energy[(size_t)B * H * T];  // energy, then score in-place

struct SmemK2 {
    __nv_bfloat16 xhi[2][128][KST];
    __nv_bfloat16 xlo[2][128][KST];
    __nv_bfloat16 whi[2][128][KST];
    __nv_bfloat16 wlo[2][128][KST];
    float q[128];
    float bias[128];
    float e[128];
};

__device__ __forceinline__ unsigned int lds32(const __nv_bfloat16* p) {
    return *reinterpret_cast<const unsigned int*>(p);
}

__device__ __forceinline__ void mma16816(float* c, const unsigned int* a, const unsigned int* b) {
    asm volatile(
        "mma.sync.aligned.m16n8k16.row.col.f32.bf16.bf16.f32 "
        "{%0,%1,%2,%3}, {%4,%5,%6,%7}, {%8,%9}, {%0,%1,%2,%3};\n"
        : "+f"(c[0]), "+f"(c[1]), "+f"(c[2]), "+f"(c[3])
        : "r"(a[0]), "r"(a[1]), "r"(a[2]), "r"(a[3]), "r"(b[0]), "r"(b[1]));
}

// ---------------------------------------------------------------------------
// Kernel 1: g_q[b, p] = relu(dec[b,:] . phi_w[p,:] + phi_b[p])
// grid (B, 8), 256 threads. One warp per output p (coalesced phi_w rows).
// ---------------------------------------------------------------------------
__global__ __launch_bounds__(256) void k1_q(
    const float* __restrict__ dec,
    const float* __restrict__ phi_w,
    const float* __restrict__ phi_b)
{
    const int b  = blockIdx.x;
    const int p0 = blockIdx.y * 128;
    __shared__ float sd[D];
    for (int i = threadIdx.x; i < D; i += 256) sd[i] = dec[b * D + i];
    __syncthreads();

    const int warp = threadIdx.x >> 5, lane = threadIdx.x & 31;
    for (int pi = warp; pi < 128; pi += 8) {
        const int p = p0 + pi;
        const float* wrow = phi_w + (size_t)p * D;
        float acc = 0.f;
        #pragma unroll 4
        for (int k = lane; k < D; k += 32) acc += sd[k] * wrow[k];
        #pragma unroll
        for (int o = 16; o; o >>= 1) acc += __shfl_xor_sync(0xffffffffu, acc, o);
        if (lane == 0) g_q[b * P + p] = fmaxf(acc + phi_b[p], 0.f);
    }
}

// ---------------------------------------------------------------------------
// Kernel 2: fused big GEMM + energy.
// Block = 256 threads (8 warps, 4x2 warp grid), C tile 128(t) x 128(n=one head).
// C = X . W_h^T via 3-term bf16-split mma.sync (hi*hi + lo*hi + hi*lo), fp32 acc.
// Epilogue: e[t] = sum_n q[n] * relu(C[t][n] + bias[n])  ->  g_energy[b,h,t].
// grid (T/128, H, B) = (32, 8, 32).
// ---------------------------------------------------------------------------
__device__ __forceinline__ void ldchunk(const float* __restrict__ Xb,
                                        const float* __restrict__ Wb,
                                        int kc, int tid, float4* rx, float4* rw)
{
    const int kb = kc * KC;
    #pragma unroll
    for (int j = 0; j < 4; j++) {
        const int idx = tid + j * 256;      // 0..1023
        const int row = idx >> 3;           // 0..127
        const int c4  = idx & 7;            // 0..7 (float4 within 32-col chunk)
        rx[j] = *reinterpret_cast<const float4*>(Xb + (size_t)row * D + kb + c4 * 4);
        rw[j] = *reinterpret_cast<const float4*>(Wb + (size_t)row * D + kb + c4 * 4);
    }
}

__device__ __forceinline__ void stchunk(SmemK2& S, int st, int tid,
                                        const float4* rx, const float4* rw)
{
    #pragma unroll
    for (int j = 0; j < 4; j++) {
        const int idx = tid + j * 256;
        const int row = idx >> 3;
        const int c4  = idx & 7;
        const float vx[4] = {rx[j].x, rx[j].y, rx[j].z, rx[j].w};
        const float vw[4] = {rw[j].x, rw[j].y, rw[j].z, rw[j].w};
        #pragma unroll
        for (int e = 0; e < 4; e++) {
            const int c = c4 * 4 + e;
            const __nv_bfloat16 hx = __float2bfloat16(vx[e]);
            S.xhi[st][row][c] = hx;
            S.xlo[st][row][c] = __float2bfloat16(vx[e] - __bfloat162float(hx));
            const __nv_bfloat16 hw = __float2bfloat16(vw[e]);
            S.whi[st][row][c] = hw;
            S.wlo[st][row][c] = __float2bfloat16(vw[e] - __bfloat162float(hw));
        }
    }
}

__global__ __launch_bounds__(256, 1) void k2_energy(
    const float* __restrict__ lis,
    const float* __restrict__ psi_w,
    const float* __restrict__ psi_b)
{
    extern __shared__ char smem_raw[];
    SmemK2& S = *reinterpret_cast<SmemK2*>(smem_raw);

    const int tid  = threadIdx.x;
    const int warp = tid >> 5, lane = tid & 31;
    const int g = lane >> 2, l = lane & 3;   // mma quad coords
    const int wm = warp >> 1, wn = warp & 1; // 4(m) x 2(n) warp grid
    const int b = blockIdx.z, h = blockIdx.y;
    const int t0 = blockIdx.x * 128;

    const float* Xb = lis + ((size_t)b * T + t0) * D;
    const float* Wb = psi_w + (size_t)h * HD * D;

    if (tid < 128) {
        S.q[tid]    = g_q[b * P + h * HD + tid];
        S.bias[tid] = psi_b[h * HD + tid];
        S.e[tid]    = 0.f;
    }

    float acc[2][8][4];
    #pragma unroll
    for (int mi = 0; mi < 2; mi++)
        #pragma unroll
        for (int ni = 0; ni < 8; ni++)
            #pragma unroll
            for (int k = 0; k < 4; k++) acc[mi][ni][k] = 0.f;

    float4 rx[4], rw[4];
    ldchunk(Xb, Wb, 0, tid, rx, rw);
    stchunk(S, 0, tid, rx, rw);

    const int NK = D / KC;  // 32
    for (int kc = 0; kc < NK; kc++) {
        __syncthreads();
        const int st = kc & 1;
        const bool pf = (kc + 1 < NK);
        if (pf) ldchunk(Xb, Wb, kc + 1, tid, rx, rw);  // overlap LDG with mma

        #pragma unroll
        for (int ks = 0; ks < 2; ks++) {
            const int kb = ks * 16 + 2 * l;
            unsigned int ahi[2][4], alo[2][4];
            #pragma unroll
            for (int mi = 0; mi < 2; mi++) {
                const int r0 = wm * 32 + mi * 16 + g;
                const __nv_bfloat16* ph = &S.xhi[st][r0][kb];
                const __nv_bfloat16* pl = &S.xlo[st][r0][kb];
                ahi[mi][0] = lds32(ph);
                ahi[mi][1] = lds32(ph + 8 * KST);
                ahi[mi][2] = lds32(ph + 8);
                ahi[mi][3] = lds32(ph + 8 * KST + 8);
                alo[mi][0] = lds32(pl);
                alo[mi][1] = lds32(pl + 8 * KST);
                alo[mi][2] = lds32(pl + 8);
                alo[mi][3] = lds32(pl + 8 * KST + 8);
            }
            #pragma unroll
            for (int ni = 0; ni < 8; ni++) {
                const int n = wn * 64 + ni * 8 + g;
                unsigned int bhi[2], blo[2];
                bhi[0] = lds32(&S.whi[st][n][kb]);
                bhi[1] = lds32(&S.whi[st][n][kb + 8]);
                blo[0] = lds32(&S.wlo[st][n][kb]);
                blo[1] = lds32(&S.wlo[st][n][kb + 8]);
                #pragma unroll
                for (int mi = 0; mi < 2; mi++) {
                    mma16816(acc[mi][ni], ahi[mi], bhi);  // hi*hi
                    mma16816(acc[mi][ni], alo[mi], bhi);  // lo*hi
                    mma16816(acc[mi][ni], ahi[mi], blo);  // hi*lo
                }
            }
        }
        if (pf) stchunk(S, st ^ 1, tid, rx, rw);
    }

    // Epilogue: bias + relu + q-weighted row sum
    float ep[4] = {0.f, 0.f, 0.f, 0.f};
    #pragma unroll
    for (int mi = 0; mi < 2; mi++) {
        #pragma unroll
        for (int ni = 0; ni < 8; ni++) {
            const int c0 = wn * 64 + ni * 8 + 2 * l;
            const float q0 = S.q[c0],    q1 = S.q[c0 + 1];
            const float b0 = S.bias[c0], b1 = S.bias[c0 + 1];
            ep[mi * 2 + 0] += q0 * fmaxf(acc[mi][ni][0] + b0, 0.f);
            ep[mi * 2 + 0] += q1 * fmaxf(acc[mi][ni][1] + b1, 0.f);
            ep[mi * 2 + 1] += q0 * fmaxf(acc[mi][ni][2] + b0, 0.f);
            ep[mi * 2 + 1] += q1 * fmaxf(acc[mi][ni][3] + b1, 0.f);
        }
    }
    #pragma unroll
    for (int o = 1; o <= 2; o <<= 1) {
        #pragma unroll
        for (int j = 0; j < 4; j++) ep[j] += __shfl_xor_sync(0xffffffffu, ep[j], o);
    }
    if (l == 0) {
        atomicAdd(&S.e[wm * 32 + g],      ep[0]);
        atomicAdd(&S.e[wm * 32 + g + 8],  ep[1]);
        atomicAdd(&S.e[wm * 32 + 16 + g], ep[2]);
        atomicAdd(&S.e[wm * 32 + 24 + g], ep[3]);
    }
    __syncthreads();
    if (tid < 128)
        g_energy[((size_t)b * H + h) * T + t0 + tid] = S.e[tid];
}

// ---------------------------------------------------------------------------
// Kernel 3: softmax over T per (b,h) row, in-place in g_energy.
// Also writes score of the LAST head (h == H-1) to out_score[b, t].
// grid (B*H), 256 threads; 16 elems per thread.
// ---------------------------------------------------------------------------
__global__ __launch_bounds__(256) void k3_softmax(float* __restrict__ out_score)
{
    const int row = blockIdx.x;          // b*H + h
    const int b = row >> 3, h = row & 7;
    float* e = g_energy + (size_t)row * T;
    const int tid = threadIdx.x;
    const int warp = tid >> 5, lane = tid & 31;

    float v[16];
    float m = -1e30f;
    #pragma unroll
    for (int i = 0; i < 16; i++) { v[i] = e[tid + i * 256]; m = fmaxf(m, v[i]); }
    #pragma unroll
    for (int o = 16; o; o >>= 1) m = fmaxf(m, __shfl_xor_sync(0xffffffffu, m, o));
    __shared__ float red[8];
    if (lane == 0) red[warp] = m;
    __syncthreads();
    m = red[0];
    #pragma unroll
    for (int w = 1; w < 8; w++) m = fmaxf(m, red[w]);

    float s = 0.f;
    #pragma unroll
    for (int i = 0; i < 16; i++) { v[i] = expf(v[i] - m); s += v[i]; }
    #pragma unroll
    for (int o = 16; o; o >>= 1) s += __shfl_xor_sync(0xffffffffu, s, o);
    __shared__ float red2[8];
    if (lane == 0) red2[warp] = s;
    __syncthreads();
    s = 0.f;
    #pragma unroll
    for (int w = 0; w < 8; w++) s += red2[w];

    const float inv = 1.f / s;
    #pragma unroll
    for (int i = 0; i < 16; i++) {
        const float sc = v[i] * inv;
        e[tid + i * 256] = sc;
        if (h == H - 1) out_score[(size_t)b * T + tid + i * 256] = sc;
    }
}

// ---------------------------------------------------------------------------
// Kernel 4: context[b, h*128+d] = sum_t score[b,h,t] * lis[b,t,h*128+d]
// grid (B*H, 8 T-splits), 256 threads (2 t-rows x 128 d). atomicAdd into
// zero-initialized output. Reads listener once (512 MB) -> HBM bound.
// ---------------------------------------------------------------------------
__global__ __launch_bounds__(256) void k4_context(
    const float* __restrict__ lis, float* __restrict__ ctx)
{
    const int bh = blockIdx.x;
    const int sidx = blockIdx.y;
    const int b = bh >> 3, h = bh & 7;
    const int tr = threadIdx.x >> 7;       // 0/1
    const int d  = threadIdx.x & 127;
    constexpr int TS = T / 8;              // 512 rows per block

    const float* lp = lis + (size_t)b * T * D + h * HD + d;
    const float* sp = g_energy + (size_t)bh * T;

    float acc = 0.f;
    const int tbeg = sidx * TS;
    #pragma unroll 4
    for (int t = tbeg + tr; t < tbeg + TS; t += 2)
        acc += sp[t] * lp[(size_t)t * D];

    __shared__ float sred[256];
    sred[threadIdx.x] = acc;
    __syncthreads();
    if (threadIdx.x < 128)
        atomicAdd(&ctx[b * D + h * HD + threadIdx.x],
                  sred[threadIdx.x] + sred[threadIdx.x + 128]);
}

// ---------------------------------------------------------------------------
// Host launch (graph-capturable: only async ops, no allocation)
// ---------------------------------------------------------------------------
extern "C" void kernel_launch(void* const* d_in, const int* in_sizes, int n_in,
                              void* d_out, int out_size)
{
    const float* dec   = (const float*)d_in[0];
    const float* lis   = (const float*)d_in[1];
    const float* phi_w = (const float*)d_in[2];
    const float* phi_b = (const float*)d_in[3];
    const float* psi_w = (const float*)d_in[4];
    const float* psi_b = (const float*)d_in[5];

    float* out = (float*)d_out;
    float* out_score = out;                       // [B, T]   (score of last head)
    float* out_ctx   = out + (size_t)B * T;       // [B, D]   (context)

    cudaFuncSetAttribute(k2_energy, cudaFuncAttributeMaxDynamicSharedMemorySize,
                         (int)sizeof(SmemK2));

    cudaMemsetAsync(out_ctx, 0, (size_t)B * D * sizeof(float));
    k1_q<<<dim3(B, 8), 256>>>(dec, phi_w, phi_b);
    k2_energy<<<dim3(T / 128, H, B), 256, sizeof(SmemK2)>>>(lis, psi_w, psi_b);
    k3_softmax<<<B * H, 256>>>(out_score);
    k4_context<<<dim3(B * H, 8), 256>>>(lis, out_ctx);
}

// round 9
// speedup vs baseline: 1.1295x; 1.1295x over previous
#include <cuda_runtime.h>
#include <cuda_bf16.h>
#include <cstdint>

// Problem constants
constexpr int B  = 32;
constexpr int T  = 4096;
constexpr int D  = 1024;
constexpr int H  = 8;
constexpr int HD = 128;
constexpr int P  = 1024;

// Device scratch (allocation-free rule: __device__ globals)
__device__ float    g_q[B * P];                   // relu(dec @ phi_w^T + phi_b)
__device__ float    g_energy[(size_t)B * H * T];  // energy, then score in-place
__device__ uint32_t g_whi[P * D / 2];             // psi_w split: bf16 hi pairs
__device__ uint32_t g_wlo[P * D / 2];             // psi_w split: bf16 lo pairs

// ---------------------------------------------------------------------------
// k2 config: per CTA M=128 (t rows), N=256 (2 heads), K chunk 32, 512 threads.
// Smem rows padded to 80B (32 bf16 + 8 pad) -> conflict-free ldmatrix/cp.async.
// ---------------------------------------------------------------------------
constexpr int KC   = 32;
constexpr int NK   = D / KC;        // 32 chunks
constexpr int SROW = 80;            // bytes per smem row
// byte offsets in dynamic smem
constexpr int SM_XH = 0;                       // [2][128*80]
constexpr int SM_XL = SM_XH + 2 * 128 * SROW;  // 20480
constexpr int SM_WH = SM_XL + 2 * 128 * SROW;  // 40960  [2][256*80]
constexpr int SM_WL = SM_WH + 2 * 256 * SROW;  // 81920
constexpr int SM_Q  = SM_WL + 2 * 256 * SROW;  // 122880 (256 f)
constexpr int SM_BI = SM_Q + 1024;             // 123904 (256 f)
constexpr int SM_E  = SM_BI + 1024;            // 124928 (256 f)
constexpr int SM_TOTAL = SM_E + 1024;          // 125952

// ---------------------------------------------------------------------------
// helpers
// ---------------------------------------------------------------------------
__device__ __forceinline__ uint32_t smem_u32(const void* p) {
    uint32_t a;
    asm("{ .reg .u64 t; cvta.to.shared.u64 t, %1; cvt.u32.u64 %0, t; }"
        : "=r"(a) : "l"(p));
    return a;
}

// Split two fp32 into packed bf16 hi pair + bf16 lo pair (x = hi + lo)
__device__ __forceinline__ void split2(float f0, float f1,
                                       uint32_t& hi, uint32_t& lo) {
    asm("cvt.rn.bf16x2.f32 %0, %1, %2;" : "=r"(hi) : "f"(f1), "f"(f0));
    const float h0 = __uint_as_float(hi << 16);
    const float h1 = __uint_as_float(hi & 0xffff0000u);
    const float l0 = f0 - h0;
    const float l1 = f1 - h1;
    asm("cvt.rn.bf16x2.f32 %0, %1, %2;" : "=r"(lo) : "f"(l1), "f"(l0));
}

__device__ __forceinline__ void sts64(uint32_t addr, uint32_t a, uint32_t b) {
    asm volatile("st.shared.v2.b32 [%0], {%1,%2};" :: "r"(addr), "r"(a), "r"(b)
                 : "memory");
}

__device__ __forceinline__ void cp_async16(uint32_t dst, const void* src) {
    asm volatile("cp.async.cg.shared.global [%0], [%1], 16;"
                 :: "r"(dst), "l"(src) : "memory");
}
__device__ __forceinline__ void cp_commit() {
    asm volatile("cp.async.commit_group;" ::: "memory");
}
__device__ __forceinline__ void cp_wait1() {
    asm volatile("cp.async.wait_group 1;" ::: "memory");
}

__device__ __forceinline__ void ldsm4(uint32_t* r, uint32_t addr) {
    asm volatile("ldmatrix.sync.aligned.m8n8.x4.shared.b16 {%0,%1,%2,%3}, [%4];"
                 : "=r"(r[0]), "=r"(r[1]), "=r"(r[2]), "=r"(r[3]) : "r"(addr));
}

__device__ __forceinline__ void mma16816(float* c, const uint32_t* a,
                                         const uint32_t* b) {
    asm volatile(
        "mma.sync.aligned.m16n8k16.row.col.f32.bf16.bf16.f32 "
        "{%0,%1,%2,%3}, {%4,%5,%6,%7}, {%8,%9}, {%0,%1,%2,%3};\n"
        : "+f"(c[0]), "+f"(c[1]), "+f"(c[2]), "+f"(c[3])
        : "r"(a[0]), "r"(a[1]), "r"(a[2]), "r"(a[3]), "r"(b[0]), "r"(b[1]));
}

// ---------------------------------------------------------------------------
// Kernel 0: split psi_w into bf16 hi/lo pair arrays (row-major [P][D])
// ---------------------------------------------------------------------------
__global__ __launch_bounds__(256) void k0_wsplit(const float* __restrict__ psi_w)
{
    const int i = blockIdx.x * 256 + threadIdx.x;   // over P*D/2
    const float2 v = reinterpret_cast<const float2*>(psi_w)[i];
    uint32_t hi, lo;
    split2(v.x, v.y, hi, lo);
    g_whi[i] = hi;
    g_wlo[i] = lo;
}

// ---------------------------------------------------------------------------
// Kernel 1: g_q[b, p] = relu(dec[b,:] . phi_w[p,:] + phi_b[p])
// ---------------------------------------------------------------------------
__global__ __launch_bounds__(256) void k1_q(
    const float* __restrict__ dec,
    const float* __restrict__ phi_w,
    const float* __restrict__ phi_b)
{
    const int b  = blockIdx.x;
    const int p0 = blockIdx.y * 128;
    __shared__ float sd[D];
    for (int i = threadIdx.x; i < D; i += 256) sd[i] = dec[b * D + i];
    __syncthreads();

    const int warp = threadIdx.x >> 5, lane = threadIdx.x & 31;
    for (int pi = warp; pi < 128; pi += 8) {
        const int p = p0 + pi;
        const float* wrow = phi_w + (size_t)p * D;
        float acc = 0.f;
        #pragma unroll 4
        for (int k = lane; k < D; k += 32) acc += sd[k] * wrow[k];
        #pragma unroll
        for (int o = 16; o; o >>= 1) acc += __shfl_xor_sync(0xffffffffu, acc, o);
        if (lane == 0) g_q[b * P + p] = fmaxf(acc + phi_b[p], 0.f);
    }
}

// ---------------------------------------------------------------------------
// Kernel 2: fused GEMM + energy via HMMA (mma.sync bf16, 3-term split).
// Grid (T/128, 4 head-pairs, B). 512 threads = 16 warps (4m x 4n).
// X: fp32 LDG -> in-register split -> STS (double buffered).
// W: pre-split bf16 via cp.async (double buffered).
// Epilogue: e[t,h] = sum_n q[n]*relu(C[t][n]+bias[n]) -> g_energy.
// ---------------------------------------------------------------------------
__global__ __launch_bounds__(512, 1) void k2_energy(
    const float* __restrict__ lis,
    const float* __restrict__ psi_b)
{
    extern __shared__ char smraw[];
    const uint32_t sb = smem_u32(smraw);

    const int tid  = threadIdx.x;
    const int warp = tid >> 5, lane = tid & 31;
    const int h0 = blockIdx.y;              // head-pair 0..3
    const int t0 = blockIdx.x * 128;
    const int b  = blockIdx.z;

    float* Sq = (float*)(smraw + SM_Q);
    float* Sb = (float*)(smraw + SM_BI);
    float* Se = (float*)(smraw + SM_E);
    if (tid < 256) {
        Sq[tid] = g_q[b * P + h0 * 256 + tid];
        Sb[tid] = psi_b[h0 * 256 + tid];
        Se[tid] = 0.f;                      // FIX: guard to 256 (smem bound)
    }

    const float* Xb = lis + ((size_t)b * T + t0) * D;
    const char* WHb = (const char*)g_whi + (size_t)(h0 * 256) * (D * 2);
    const char* WLb = (const char*)g_wlo + (size_t)(h0 * 256) * (D * 2);

    // ldmatrix lane offsets (within a 16x16 tile, row stride SROW)
    const int l7 = lane & 7;
    const uint32_t aoff = (uint32_t)((l7 + 8 * ((lane >> 3) & 1)) * SROW +
                                     16 * (lane >> 4));
    const uint32_t boff = (uint32_t)((l7 + 8 * (lane >> 4)) * SROW +
                                     16 * ((lane >> 3) & 1));

    const int wm = warp >> 2, wn = warp & 3;
    const int m0 = wm * 32, n0 = wn * 64;

    float acc[2][8][4];
    #pragma unroll
    for (int mi = 0; mi < 2; mi++)
        #pragma unroll
        for (int ni = 0; ni < 8; ni++)
            #pragma unroll
            for (int k = 0; k < 4; k++) acc[mi][ni][k] = 0.f;

    // prologue: LDG X(0), cp.async W(0)
    float4 xr[2];
    #pragma unroll
    for (int j = 0; j < 2; j++) {
        const int q = tid + j * 512;
        xr[j] = *reinterpret_cast<const float4*>(Xb + (size_t)(q >> 3) * D + (q & 7) * 4);
    }
    #pragma unroll
    for (int j = 0; j < 4; j++) {
        const int q = tid + j * 512;            // 0..2047
        const int half = q >> 10;               // 0 hi, 1 lo
        const int r = (q >> 2) & 255;
        const int g16 = q & 3;
        const char* src = (half ? WLb : WHb) + (size_t)r * (D * 2) + g16 * 16;
        const uint32_t dst = sb + (half ? SM_WL : SM_WH) + r * SROW + g16 * 16;
        cp_async16(dst, src);
    }
    cp_commit();

    for (int kc = 0; kc < NK; kc++) {
        const int st = kc & 1;
        const uint32_t xh = sb + SM_XH + st * (128 * SROW);
        const uint32_t xl = sb + SM_XL + st * (128 * SROW);
        const uint32_t wh = sb + SM_WH + st * (256 * SROW);
        const uint32_t wl = sb + SM_WL + st * (256 * SROW);

        __syncthreads();   // A: readers of stage st (X) / st^1 (W cp target) done

        // STS X(kc) from regs into stage st
        #pragma unroll
        for (int j = 0; j < 2; j++) {
            const int q = tid + j * 512;
            const int row = q >> 3, c4 = q & 7;
            uint32_t h01, l01, h23, l23;
            split2(xr[j].x, xr[j].y, h01, l01);
            split2(xr[j].z, xr[j].w, h23, l23);
            const uint32_t a = (uint32_t)(row * SROW + c4 * 8);
            sts64(xh + a, h01, h23);
            sts64(xl + a, l01, l23);
        }

        const bool more = (kc + 1 < NK);
        if (more) {
            const int kb2 = (kc + 1) * KC;
            #pragma unroll
            for (int j = 0; j < 4; j++) {
                const int q = tid + j * 512;
                const int half = q >> 10;
                const int r = (q >> 2) & 255;
                const int g16 = q & 3;
                const char* src = (half ? WLb : WHb) + (size_t)r * (D * 2) +
                                  kb2 * 2 + g16 * 16;
                const uint32_t dst = sb + (half ? SM_WL : SM_WH) +
                                     (st ^ 1) * (256 * SROW) + r * SROW + g16 * 16;
                cp_async16(dst, src);
            }
        }
        cp_commit();
        if (more) {
            const int kb2 = (kc + 1) * KC;
            #pragma unroll
            for (int j = 0; j < 2; j++) {
                const int q = tid + j * 512;
                xr[j] = *reinterpret_cast<const float4*>(
                    Xb + (size_t)(q >> 3) * D + kb2 + (q & 7) * 4);
            }
        }

        cp_wait1();        // W(kc) arrived
        __syncthreads();   // B: X(kc) visible to all

        #pragma unroll
        for (int ks = 0; ks < 2; ks++) {
            const uint32_t kofs = (uint32_t)(ks * 32);   // 16 bf16 = 32 bytes
            uint32_t ahi[2][4], alo[2][4];
            #pragma unroll
            for (int mi = 0; mi < 2; mi++) {
                const uint32_t rb = (uint32_t)((m0 + 16 * mi) * SROW) + kofs;
                ldsm4(ahi[mi], xh + rb + aoff);
                ldsm4(alo[mi], xl + rb + aoff);
            }
            #pragma unroll
            for (int np = 0; np < 4; np++) {
                const uint32_t rb = (uint32_t)((n0 + 16 * np) * SROW) + kofs;
                uint32_t bh[4], bl[4];
                ldsm4(bh, wh + rb + boff);
                ldsm4(bl, wl + rb + boff);
                #pragma unroll
                for (int mi = 0; mi < 2; mi++) {
                    mma16816(acc[mi][2 * np],     ahi[mi], bh);       // hi*hi
                    mma16816(acc[mi][2 * np + 1], ahi[mi], bh + 2);
                    mma16816(acc[mi][2 * np],     alo[mi], bh);       // lo*hi
                    mma16816(acc[mi][2 * np + 1], alo[mi], bh + 2);
                    mma16816(acc[mi][2 * np],     ahi[mi], bl);       // hi*lo
                    mma16816(acc[mi][2 * np + 1], ahi[mi], bl + 2);
                }
            }
        }
    }

    // Epilogue: e[row] += q[col]*relu(acc+bias[col]); reduce over quad lanes
    const int g = lane >> 2, l = lane & 3;
    float ep[2][2] = {{0.f, 0.f}, {0.f, 0.f}};
    #pragma unroll
    for (int mi = 0; mi < 2; mi++) {
        #pragma unroll
        for (int ni = 0; ni < 8; ni++) {
            const int c0 = n0 + ni * 8 + 2 * l;
            const float q0 = Sq[c0],  q1 = Sq[c0 + 1];
            const float b0 = Sb[c0],  b1 = Sb[c0 + 1];
            ep[mi][0] += q0 * fmaxf(acc[mi][ni][0] + b0, 0.f)
                       + q1 * fmaxf(acc[mi][ni][1] + b1, 0.f);
            ep[mi][1] += q0 * fmaxf(acc[mi][ni][2] + b0, 0.f)
                       + q1 * fmaxf(acc[mi][ni][3] + b1, 0.f);
        }
    }
    #pragma unroll
    for (int o = 1; o <= 2; o <<= 1) {
        #pragma unroll
        for (int mi = 0; mi < 2; mi++) {
            ep[mi][0] += __shfl_xor_sync(0xffffffffu, ep[mi][0], o);
            ep[mi][1] += __shfl_xor_sync(0xffffffffu, ep[mi][1], o);
        }
    }
    const int hh = wn >> 1;                  // head within pair
    if (l == 0) {
        #pragma unroll
        for (int mi = 0; mi < 2; mi++) {
            atomicAdd(&Se[(hh << 7) + m0 + 16 * mi + g],     ep[mi][0]);
            atomicAdd(&Se[(hh << 7) + m0 + 16 * mi + 8 + g], ep[mi][1]);
        }
    }
    __syncthreads();
    if (tid < 256)
        g_energy[((size_t)b * H + h0 * 2 + (tid >> 7)) * T + t0 + (tid & 127)] =
            Se[tid];
}

// ---------------------------------------------------------------------------
// Kernel 3: softmax over T per (b,h) row, in-place in g_energy.
// Writes score of the LAST head to out_score[b, t].
// ---------------------------------------------------------------------------
__global__ __launch_bounds__(256) void k3_softmax(float* __restrict__ out_score)
{
    const int row = blockIdx.x;          // b*H + h
    const int h = row & 7, b = row >> 3;
    float* e = g_energy + (size_t)row * T;
    const int tid = threadIdx.x;
    const int warp = tid >> 5, lane = tid & 31;

    float v[16];
    float m = -1e30f;
    #pragma unroll
    for (int i = 0; i < 16; i++) { v[i] = e[tid + i * 256]; m = fmaxf(m, v[i]); }
    #pragma unroll
    for (int o = 16; o; o >>= 1) m = fmaxf(m, __shfl_xor_sync(0xffffffffu, m, o));
    __shared__ float red[8];
    if (lane == 0) red[warp] = m;
    __syncthreads();
    m = red[0];
    #pragma unroll
    for (int w = 1; w < 8; w++) m = fmaxf(m, red[w]);

    float s = 0.f;
    #pragma unroll
    for (int i = 0; i < 16; i++) { v[i] = expf(v[i] - m); s += v[i]; }
    #pragma unroll
    for (int o = 16; o; o >>= 1) s += __shfl_xor_sync(0xffffffffu, s, o);
    __shared__ float red2[8];
    if (lane == 0) red2[warp] = s;
    __syncthreads();
    s = 0.f;
    #pragma unroll
    for (int w = 0; w < 8; w++) s += red2[w];

    const float inv = 1.f / s;
    #pragma unroll
    for (int i = 0; i < 16; i++) {
        const float sc = v[i] * inv;
        e[tid + i * 256] = sc;
        if (h == H - 1) out_score[(size_t)b * T + tid + i * 256] = sc;
    }
}

// ---------------------------------------------------------------------------
// Kernel 4: context[b, h*128+d] = sum_t score[b,h,t] * lis[b,t,h*128+d]
// ---------------------------------------------------------------------------
__global__ __launch_bounds__(256) void k4_context(
    const float* __restrict__ lis, float* __restrict__ ctx)
{
    const int bh = blockIdx.x;
    const int sidx = blockIdx.y;
    const int b = bh >> 3, h = bh & 7;
    const int tr = threadIdx.x >> 7;       // 0/1
    const int d  = threadIdx.x & 127;
    constexpr int TS = T / 8;              // 512 rows per block

    const float* lp = lis + (size_t)b * T * D + h * HD + d;
    const float* sp = g_energy + (size_t)bh * T;

    float acc = 0.f;
    const int tbeg = sidx * TS;
    #pragma unroll 4
    for (int t = tbeg + tr; t < tbeg + TS; t += 2)
        acc += sp[t] * lp[(size_t)t * D];

    __shared__ float sred[256];
    sred[threadIdx.x] = acc;
    __syncthreads();
    if (threadIdx.x < 128)
        atomicAdd(&ctx[b * D + h * HD + threadIdx.x],
                  sred[threadIdx.x] + sred[threadIdx.x + 128]);
}

// ---------------------------------------------------------------------------
// Host launch (graph-capturable: only async ops, no allocation)
// ---------------------------------------------------------------------------
extern "C" void kernel_launch(void* const* d_in, const int* in_sizes, int n_in,
                              void* d_out, int out_size)
{
    const float* dec   = (const float*)d_in[0];
    const float* lis   = (const float*)d_in[1];
    const float* phi_w = (const float*)d_in[2];
    const float* phi_b = (const float*)d_in[3];
    const float* psi_w = (const float*)d_in[4];
    const float* psi_b = (const float*)d_in[5];

    float* out = (float*)d_out;
    float* out_score = out;                       // [B, T]  (score of last head)
    float* out_ctx   = out + (size_t)B * T;       // [B, D]  (context)

    cudaFuncSetAttribute(k2_energy, cudaFuncAttributeMaxDynamicSharedMemorySize,
                         SM_TOTAL);

    cudaMemsetAsync(out_ctx, 0, (size_t)B * D * sizeof(float));
    k0_wsplit<<<P * D / 2 / 256, 256>>>(psi_w);
    k1_q<<<dim3(B, 8), 256>>>(dec, phi_w, phi_b);
    k2_energy<<<dim3(T / 128, 4, B), 512, SM_TOTAL>>>(lis, psi_b);
    k3_softmax<<<B * H, 256>>>(out_score);
    k4_context<<<dim3(B * H, 8), 256>>>(lis, out_ctx);
}